// round 13
// baseline (speedup 1.0000x reference)
#include <cuda_runtime.h>
#include <math_constants.h>

// Hausdorff distance between edge sets of two binary 128^3 masks, batch=2.
// SINGLE persistent kernel, 256 blocks x 256 threads, software grid barriers:
//   Phase 1: binarize inputs -> bit-packed masks (float4 + shfl words)
//   Phase 2: per (v,z) slice: bitwise 3x3x3 edge + exact 1D x-distance g
//            (smem slice) + worklist compaction + Meijster envelope along y
//            -> dt2 = exact 2D squared EDT (u16). 2 slices per block.
//   Phase 3: one thread per partner edge voxel: exact min over z within a
//            precomputed radius bound -> directed max -> sqrt -> out[2].
// Grid barriers use a monotonic generation counter (graph-replay safe); the
// gpu-scope __threadfence on the exit path invalidates L1D (CCTL.IVALL), so
// post-barrier plain loads observe other SMs' writes.

#define DWH 128
#define NVOL 4                      // (b0,in) (b0,tgt) (b1,in) (b1,tgt)
#define VOXELS (128 * 128 * 128)
#define GCLAMP 222                  // 222^2 = 49284 > 3*127^2 -> lossless clamp
#define GPITCH 132                  // smem g row pitch (33 words, stride 1 bank)
#define NBLOCKS 256
#define NTHREADS 256

// ---- scratch: __device__ globals (no allocation allowed) ----
__device__ unsigned int   g_mask[NVOL][DWH][DWH][4];  // bit-packed masks, 1MB
__device__ unsigned short g_dt2[NVOL][VOXELS];        // 2D sq-EDT per slice, 16MB
__device__ unsigned int   g_list[NVOL][VOXELS];       // packed edge coords, 32MB
__device__ int            g_cnt[NVOL];                // edge counts / list sizes
__device__ int            g_dirmax[NVOL];             // directed max squared EDT
__device__ unsigned int          g_barCnt;            // barrier arrive counter
__device__ volatile unsigned int g_barGen;            // barrier generation (monotonic)

// Grid-wide barrier. All NBLOCKS blocks resident (see launch_bounds note).
// gen is monotonic across uses AND graph replays; cnt self-resets. The
// gpu-scope __threadfence on exit invalidates this SM's L1D, making other
// SMs' plain global writes visible to subsequent plain loads.
__device__ __forceinline__ void grid_barrier()
{
    __syncthreads();
    if (threadIdx.x == 0) {
        __threadfence();                              // publish phase writes
        unsigned int gen = g_barGen;
        if (atomicAdd(&g_barCnt, 1u) == (unsigned int)(NBLOCKS - 1)) {
            g_barCnt = 0;                             // safe: all have arrived
            __threadfence();
            g_barGen = gen + 1;                       // release (volatile store)
        } else {
            while (g_barGen == gen) __nanosleep(64);
        }
        __threadfence();                              // acquire + L1D invalidate
    }
    __syncthreads();
}

__global__ void __launch_bounds__(NTHREADS, 2) k_hausdorff(
    const float* __restrict__ inputs, const float* __restrict__ targets,
    float* __restrict__ out)
{
    __shared__ unsigned char gsm[2][128 * GPITCH];    // 2 slices, 33.8 KB
    __shared__ int wmax[8];

    int tid  = threadIdx.x;
    int bid  = blockIdx.x;
    int lane = tid & 31;

    // ======================= Phase 1: binarize =======================
    // One warp per 128-float row (grid-stride, 32 rows/warp). Lane loads
    // float4 (x = lane*4..+3) -> nibble at bit (lane&7)*4 -> 3-step shfl_xor
    // OR assembles each oct's 32-bit word; lanes 0/8/16/24 store words 0..3.
    // [row body byte-identical to the R12 passing kernel]
    if (bid == 0 && tid < 8) {
        if (tid < 4) g_cnt[tid] = 0;
        else         g_dirmax[tid - 4] = 0;
    }
    {
        int wg = bid * (NTHREADS / 32) + (tid >> 5);  // 2048 warps
        for (int r = wg; r < 65536; r += NBLOCKS * (NTHREADS / 32)) {
            int v = r >> 14;
            int z = (r >> 7) & 127;
            int y = r & 127;
            const float* src = (v & 1) ? targets : inputs;
            int b = v >> 1;
            const float4* row =
                (const float4*)(src + (size_t)b * VOXELS + z * 16384 + y * 128);
            float4 val = row[lane];
            unsigned int nib = (val.x > 0.0f ? 1u : 0u)
                             | (val.y > 0.0f ? 2u : 0u)
                             | (val.z > 0.0f ? 4u : 0u)
                             | (val.w > 0.0f ? 8u : 0u);
            unsigned int u = nib << ((lane & 7) * 4);
            u |= __shfl_xor_sync(0xFFFFFFFFu, u, 1);
            u |= __shfl_xor_sync(0xFFFFFFFFu, u, 2);
            u |= __shfl_xor_sync(0xFFFFFFFFu, u, 4);
            if ((lane & 7) == 0) g_mask[v][z][y][lane >> 3] = u;
        }
    }
    grid_barrier();

    // ================ Phase 2: edge + envelope (2 slices/block) ================
    {
        int half  = tid >> 7;                         // 0 or 1
        int slice = bid * 2 + half;                   // 0..511
        int v = slice >> 7;
        int z = slice & 127;
        int y = tid & 127;                            // stage A: thread = y-row
        unsigned char* gs = gsm[half];

        // ---- stage A: edge bits for row (v,z,y) ----
        unsigned int a0 = 0, a1 = 0, a2 = 0, a3 = 0;
        #pragma unroll
        for (int dz = -1; dz <= 1; dz++) {
            int zz = z + dz;
            if (zz < 0 || zz > 127) continue;
            #pragma unroll
            for (int dy = -1; dy <= 1; dy++) {
                int yy = y + dy;
                if (yy < 0 || yy > 127) continue;
                const unsigned int* r = g_mask[v][zz][yy];
                a0 |= r[0]; a1 |= r[1]; a2 |= r[2]; a3 |= r[3];
            }
        }
        unsigned int d0 = a0 | (a0 << 1)               | (a0 >> 1) | (a1 << 31);
        unsigned int d1 = a1 | (a1 << 1) | (a0 >> 31)  | (a1 >> 1) | (a2 << 31);
        unsigned int d2 = a2 | (a2 << 1) | (a1 >> 31)  | (a2 >> 1) | (a3 << 31);
        unsigned int d3 = a3 | (a3 << 1) | (a2 >> 31)  | (a3 >> 1);

        const unsigned int* m = g_mask[v][z][y];
        unsigned int ew[4];
        ew[0] = d0 & ~m[0]; ew[1] = d1 & ~m[1]; ew[2] = d2 & ~m[2]; ew[3] = d3 & ~m[3];

        // ---- worklist append (one reservation per row with any edges) ----
        int cnt = __popc(ew[0]) + __popc(ew[1]) + __popc(ew[2]) + __popc(ew[3]);
        if (cnt) {
            int idx = atomicAdd(&g_cnt[v], cnt);
            unsigned int* lst = g_list[v];
            unsigned int zy = ((unsigned int)z << 14) | ((unsigned int)y << 7);
            #pragma unroll
            for (int w = 0; w < 4; w++) {
                unsigned int bits = ew[w];
                while (bits) {
                    int bit = __ffs(bits) - 1;
                    bits &= bits - 1;
                    lst[idx++] = zy | (unsigned int)(w * 32 + bit);
                }
            }
        }

        // ---- 1D x-distance g (exact, clamped), registers -> smem ----
        unsigned int gr[32];
        {
            int g = GCLAMP;
            #pragma unroll
            for (int w4 = 0; w4 < 32; w4++) {
                unsigned int word = ew[w4 >> 3];
                unsigned int packed = 0;
                #pragma unroll
                for (int j = 0; j < 4; j++) {
                    int bit = (word >> (((w4 & 7) << 2) + j)) & 1;
                    g = bit ? 0 : (g < GCLAMP ? g + 1 : GCLAMP);
                    packed |= (unsigned int)g << (8 * j);
                }
                gr[w4] = packed;
            }
            int p = (gr[31] >> 24) & 0xFF;
            #pragma unroll
            for (int x = 126; x >= 0; x--) {
                int w4 = x >> 2, sh = (x & 3) << 3;
                int c = (gr[w4] >> sh) & 0xFF;
                int nv = p + 1;
                if (c < nv) nv = c;
                gr[w4] = (gr[w4] & ~(0xFFu << sh)) | ((unsigned int)nv << sh);
                p = nv;
            }
        }
        {
            unsigned int* row = (unsigned int*)&gs[y * GPITCH]; // 132 % 4 == 0
            #pragma unroll
            for (int i = 0; i < 32; i++) row[i] = gr[i];
        }
        __syncthreads();

        // ---- stage B: Meijster envelope along y, thread = x column ----
        {
            int x = tid & 127;
            const unsigned char* gcol = &gs[x];

            short          stS[128];
            short          stT[128];
            unsigned short stF[128];

            int q  = 0;
            int sq = 0, tq = 0;
            int g0 = gcol[0];
            int fsq = g0 * g0;

            #pragma unroll 4
            for (int u = 1; u < 128; u++) {
                int gu = gcol[u * GPITCH];
                int fu = gu * gu;
                for (;;) {
                    int aa = tq - sq, bb = tq - u;
                    if (aa * aa + fsq > bb * bb + fu) {
                        if (q == 0) { q = -1; break; }
                        q--; sq = stS[q]; tq = stT[q]; fsq = stF[q];
                    } else break;
                }
                if (q < 0) { q = 0; sq = u; tq = 0; fsq = fu; }
                else {
                    int w = 1 + (u * u - sq * sq + fu - fsq) / (2 * (u - sq));
                    if (w < 128) {
                        stS[q] = (short)sq; stT[q] = (short)tq;
                        stF[q] = (unsigned short)fsq;
                        q++; sq = u; tq = w; fsq = fu;
                    }
                }
            }

            unsigned short* dt = &g_dt2[v][z * 16384 + x];
            #pragma unroll 4
            for (int u = 127; u >= 0; u--) {
                int d = u - sq;
                dt[u * 128] = (unsigned short)(d * d + fsq);
                if (u == tq) {
                    q--;
                    if (q >= 0) { sq = stS[q]; tq = stT[q]; fsq = stF[q]; }
                }
            }
        }
    }
    grid_barrier();

    // ======================= Phase 3: z-min gather =======================
    // Blocks with bid%4 == qv handle volume qv (64 blocks x 256 thr each).
    {
        int qv = bid & 3;
        int pv = qv ^ 1;
        int cnt = g_cnt[qv];                 // post-barrier load: L1 invalidated
        int lmax = -1;
        const unsigned int*   lst  = g_list[qv];
        const unsigned short* dtpv = g_dt2[pv];

        for (int i = (bid >> 2) * NTHREADS + tid; i < cnt; i += 64 * NTHREADS) {
            unsigned int e = lst[i];
            int x = e & 127;
            int y = (int)(e >> 7) & 127;
            int z = (int)(e >> 14);

            const unsigned short* col = dtpv + y * 128 + x;
            int best = (int)col[z * 16384];            // tight exact bound (dz=0)
            int dzmax = (int)sqrtf((float)best) + 1;   // safe overshoot
            int zlo = z - dzmax; if (zlo < 0) zlo = 0;
            int zhi = z + dzmax; if (zhi > 127) zhi = 127;
            #pragma unroll 4
            for (int zz = zlo; zz <= zhi; zz++) {
                int d = z - zz;
                int c = d * d + (int)col[zz * 16384];  // independent loads
                if (c < best) best = c;
            }
            if (best > lmax) lmax = best;
        }

        // block max over 256 threads -> one atomic per block
        #pragma unroll
        for (int off = 16; off; off >>= 1) {
            int o = __shfl_down_sync(0xFFFFFFFFu, lmax, off);
            if (o > lmax) lmax = o;
        }
        if (lane == 0) wmax[tid >> 5] = lmax;
        __syncthreads();
        if (tid == 0) {
            int m = wmax[0];
            #pragma unroll
            for (int i = 1; i < 8; i++) if (wmax[i] > m) m = wmax[i];
            if (m >= 0) atomicMax(&g_dirmax[qv], m);
        }
    }
    grid_barrier();

    // ======================= Finalize =======================
    if (bid == 0 && tid < 2) {
        int vA = 2 * tid, vB = 2 * tid + 1;
        bool empty = (g_cnt[vA] == 0) || (g_cnt[vB] == 0);
        int mA = atomicAdd(&g_dirmax[vA], 0);          // L2 reads
        int mB = atomicAdd(&g_dirmax[vB], 0);
        int m  = mA > mB ? mA : mB;
        out[tid] = empty ? CUDART_INF_F : sqrtf((float)m);
    }
}

// ============================================================================
extern "C" void kernel_launch(void* const* d_in, const int* in_sizes, int n_in,
                              void* d_out, int out_size)
{
    const float* inputs  = (const float*)d_in[0];
    const float* targets = (const float*)d_in[1];
    float* out = (float*)d_out;

    k_hausdorff<<<NBLOCKS, NTHREADS>>>(inputs, targets, out);
}

// round 14
// speedup vs baseline: 1.2524x; 1.2524x over previous
#include <cuda_runtime.h>
#include <math_constants.h>

// Hausdorff distance between edge sets of two binary 128^3 masks, batch=2.
// Pipeline: bit-pack masks (float4 + shfl-assembled words) -> [fused] bitwise
// 3x3x3 edge extraction + exact 1D x-distance g (u8, via smem slice) +
// edge-voxel worklist compaction + Meijster envelope along y -> dt2 = exact
// 2D squared EDT per z-slice (u16) -> one thread per partner edge voxel:
// exact min over z within a precomputed radius bound -> directed max ->
// sqrt. Output: 2 floats.

#define DWH 128
#define NVOL 4                      // (b0,in) (b0,tgt) (b1,in) (b1,tgt)
#define VOXELS (128 * 128 * 128)
#define GCLAMP 222                  // 222^2 = 49284 > 3*127^2 -> lossless clamp
#define GPITCH 132                  // smem g row pitch (33 words, stride 1 bank)

// ---- scratch: __device__ globals (no allocation allowed) ----
__device__ unsigned int   g_mask[NVOL][DWH][DWH][4];  // bit-packed masks, 1MB
__device__ unsigned short g_dt2[NVOL][VOXELS];        // 2D sq-EDT per slice, 16MB
__device__ unsigned int   g_list[NVOL][VOXELS];       // packed edge coords, 32MB
__device__ int            g_cnt[NVOL];                // edge counts / list sizes
__device__ int            g_dirmax[NVOL];             // directed max squared EDT
__device__ unsigned int   g_done;                     // k_zmin completion counter

// ============================================================================
// Kernel 1: binarize inputs (>0) into bit-packed masks.  [validated R12]
// One warp per 128-float row; lane loads float4 -> nibble -> 3-step shfl_xor
// OR assembles each oct's 32-bit word; lanes 0/8/16/24 store words 0..3.
// Also zeroes the accumulators (consumed only by later kernels).
// ============================================================================
__global__ void __launch_bounds__(256) k_binarize(
    const float* __restrict__ inputs, const float* __restrict__ targets)
{
    int gt = blockIdx.x * blockDim.x + threadIdx.x;   // 2,097,152 threads
    if (gt < 9) {
        if (gt < 4)      g_cnt[gt] = 0;
        else if (gt < 8) g_dirmax[gt - 4] = 0;
        else             g_done = 0;
    }
    int lane = gt & 31;
    int wrp  = gt >> 5;              // 65536 warps, one per (v,z,y) row
    int v    = wrp >> 14;
    int rem  = wrp & 16383;
    int z    = rem >> 7;
    int y    = rem & 127;

    const float* src = (v & 1) ? targets : inputs;
    int b = v >> 1;
    const float4* row = (const float4*)(src + (size_t)b * VOXELS + z * 16384 + y * 128);
    float4 val = row[lane];

    unsigned int nib = (val.x > 0.0f ? 1u : 0u)
                     | (val.y > 0.0f ? 2u : 0u)
                     | (val.z > 0.0f ? 4u : 0u)
                     | (val.w > 0.0f ? 8u : 0u);
    unsigned int u = nib << ((lane & 7) * 4);
    u |= __shfl_xor_sync(0xFFFFFFFFu, u, 1);
    u |= __shfl_xor_sync(0xFFFFFFFFu, u, 2);
    u |= __shfl_xor_sync(0xFFFFFFFFu, u, 4);          // full word per 8-lane oct
    if ((lane & 7) == 0) g_mask[v][z][y][lane >> 3] = u;
}

// Exact C-truncation division num/den (den>0) via fast float divide + fixup.
// |num| < 2^17, den <= 254 -> float quotient error << 1 -> one-step fix.
__device__ __forceinline__ int trunc_div(int num, int den)
{
    int q = __float2int_rz(__fdividef((float)num, (float)den));
    int r = num - q * den;
    if (num >= 0) { q += (r >= den); q -= (r < 0); }
    else          { q += (r > 0);    q -= (r <= -den); }
    return q;
}

// ============================================================================
// Kernel 2 (FUSED edge + phase2), one block per (v,z) slice, 128 threads.
// Stage A (thread = y-row): edge = (~mask) & (3x3x3 box-OR of mask) bitwise;
//   worklist append; exact 1D x-distance g (u8, register byte-array) staged
//   into a smem slice [y][x] (pitch 132: conflict-free both ways).
//   [byte-identical to R12 passing kernel]
// Stage B (thread = x-column): Meijster lower envelope along y over smem g:
//   dt2(x,y,z) = min_yy (y-yy)^2 + g(x,yy,z)^2  (exact 2D squared EDT).
//   NEW: fast exact division (trunc_div), stack entries packed into one u32
//   (sq:7|tq:7|fsq:16 -- tq in [0,127] since sep > surviving top's tq,
//   fsq <= 49284), next-g smem load software-pipelined. Values identical to
//   the validated integer version. Max dt2 = 65413 < 65536 -> u16 no clamp.
// ============================================================================
__global__ void __launch_bounds__(128) k_edgephase2()
{
    __shared__ unsigned char gsm[128 * GPITCH];       // 16.9 KB g slice [y][x]

    int b = blockIdx.x;                  // 512 = 4 volumes * 128 z-slices
    int v = b >> 7;
    int z = b & 127;
    int y = threadIdx.x;                 // stage A: thread = y-row

    // ---- stage A: edge bits for row (v,z,y) ----
    unsigned int a0 = 0, a1 = 0, a2 = 0, a3 = 0;
    #pragma unroll
    for (int dz = -1; dz <= 1; dz++) {
        int zz = z + dz;
        if (zz < 0 || zz > 127) continue;
        #pragma unroll
        for (int dy = -1; dy <= 1; dy++) {
            int yy = y + dy;
            if (yy < 0 || yy > 127) continue;
            const unsigned int* r = g_mask[v][zz][yy];
            a0 |= r[0]; a1 |= r[1]; a2 |= r[2]; a3 |= r[3];
        }
    }
    // dilate along x across the 128-bit row (word carries)
    unsigned int d0 = a0 | (a0 << 1)               | (a0 >> 1) | (a1 << 31);
    unsigned int d1 = a1 | (a1 << 1) | (a0 >> 31)  | (a1 >> 1) | (a2 << 31);
    unsigned int d2 = a2 | (a2 << 1) | (a1 >> 31)  | (a2 >> 1) | (a3 << 31);
    unsigned int d3 = a3 | (a3 << 1) | (a2 >> 31)  | (a3 >> 1);

    const unsigned int* m = g_mask[v][z][y];
    unsigned int ew[4];
    ew[0] = d0 & ~m[0]; ew[1] = d1 & ~m[1]; ew[2] = d2 & ~m[2]; ew[3] = d3 & ~m[3];

    // ---- worklist append (one reservation per row with any edges) ----
    int cnt = __popc(ew[0]) + __popc(ew[1]) + __popc(ew[2]) + __popc(ew[3]);
    if (cnt) {
        int idx = atomicAdd(&g_cnt[v], cnt);
        unsigned int* lst = g_list[v];
        unsigned int zy = ((unsigned int)z << 14) | ((unsigned int)y << 7);
        #pragma unroll
        for (int w = 0; w < 4; w++) {
            unsigned int bits = ew[w];
            while (bits) {
                int bit = __ffs(bits) - 1;
                bits &= bits - 1;
                lst[idx++] = zy | (unsigned int)(w * 32 + bit);
            }
        }
    }

    // ---- 1D x-distance g (exact, clamped at GCLAMP), registers -> smem ----
    unsigned int gr[32];                 // 128 u8 packed, static-indexed -> regs
    {
        int g = GCLAMP;
        #pragma unroll
        for (int w4 = 0; w4 < 32; w4++) {              // packs x = 4*w4 .. +3
            unsigned int word = ew[w4 >> 3];
            unsigned int packed = 0;
            #pragma unroll
            for (int j = 0; j < 4; j++) {
                int bit = (word >> (((w4 & 7) << 2) + j)) & 1;
                g = bit ? 0 : (g < GCLAMP ? g + 1 : GCLAMP);
                packed |= (unsigned int)g << (8 * j);
            }
            gr[w4] = packed;
        }
        int p = (gr[31] >> 24) & 0xFF;
        #pragma unroll
        for (int x = 126; x >= 0; x--) {
            int w4 = x >> 2, sh = (x & 3) << 3;
            int c = (gr[w4] >> sh) & 0xFF;
            int nv = p + 1;
            if (c < nv) nv = c;                        // nv <= GCLAMP always
            gr[w4] = (gr[w4] & ~(0xFFu << sh)) | ((unsigned int)nv << sh);
            p = nv;
        }
    }
    {
        unsigned int* row = (unsigned int*)&gsm[y * GPITCH];  // 132 % 4 == 0
        #pragma unroll
        for (int i = 0; i < 32; i++) row[i] = gr[i];   // stride-33-word: no bank conflicts
    }
    __syncthreads();

    // ---- stage B: Meijster envelope along y, thread = x column ----
    {
        int x = threadIdx.x;
        const unsigned char* gcol = &gsm[x];

        unsigned int stPk[128];          // packed stack below the register top

        int q  = 0;                      // top level; stack[0..q-1] in memory
        int sq = 0, tq = 0;
        int g0 = gcol[0];
        int fsq = g0 * g0;

        int gu = gcol[GPITCH];           // prefetched g[1]
        for (int u = 1; u < 128; u++) {
            int fu = gu * gu;
            int unext = (u < 127) ? u + 1 : 127;
            gu = gcol[unext * GPITCH];   // prefetch next (overlaps envelope ALU)

            for (;;) {
                int aa = tq - sq, bb = tq - u;
                if (aa * aa + fsq > bb * bb + fu) {    // incumbent loses at tq
                    if (q == 0) { q = -1; break; }
                    q--;
                    unsigned int pk = stPk[q];
                    sq = pk & 127; tq = (pk >> 7) & 127; fsq = pk >> 14;
                } else break;
            }
            if (q < 0) { q = 0; sq = u; tq = 0; fsq = fu; }
            else {
                int du  = u - sq;                       // 1..127
                int num = (u + sq) * du + fu - fsq;     // u^2 - sq^2 + fu - fsq
                int w   = 1 + trunc_div(num, 2 * du);
                if (w < 128) {
                    stPk[q] = (unsigned int)sq | ((unsigned int)tq << 7)
                            | ((unsigned int)fsq << 14);
                    q++; sq = u; tq = w; fsq = fu;
                }
            }
        }

        unsigned short* dt = &g_dt2[v][z * 16384 + x];
        #pragma unroll 4
        for (int u = 127; u >= 0; u--) {
            int d = u - sq;
            dt[u * 128] = (unsigned short)(d * d + fsq);
            if (u == tq) {
                q--;
                if (q >= 0) {
                    unsigned int pk = stPk[q];
                    sq = pk & 127; tq = (pk >> 7) & 127; fsq = pk >> 14;
                }
            }
        }
    }
}

// ============================================================================
// Kernel 3: one thread per partner edge voxel (grid-stride over the compacted
// worklist). For voxel q=(x,y,z) of volume qv:
//   EDT(q) = min_zz (z-zz)^2 + dt2_pv(x,y,zz)
// best0 = dt2_pv at zz=z (exact in-slice EDT) -> radius bound
// dzmax = floor(sqrt(best0))+1 (overshoot harmless). All threads independent.
// Directed max -> atomicMax; last finished block writes both outputs
// (atomic reads bypass a stale L1 line shared with g_cnt). [validated R10-R12]
// ============================================================================
__global__ void __launch_bounds__(128) k_zmin(float* __restrict__ out)
{
    int b   = blockIdx.x;                // 1024
    int qv  = b & 3;
    int pv  = qv ^ 1;
    int tid = threadIdx.x;

    int cnt = g_cnt[qv];                 // list size for this volume
    int lmax = -1;
    const unsigned int*   lst  = g_list[qv];
    const unsigned short* dtpv = g_dt2[pv];

    for (int i = (b >> 2) * 128 + tid; i < cnt; i += 256 * 128) {
        unsigned int e = lst[i];
        int x = e & 127;
        int y = (int)(e >> 7) & 127;
        int z = (int)(e >> 14);

        const unsigned short* col = dtpv + y * 128 + x;
        int best = (int)col[z * 16384];            // tight exact bound (dz=0)
        int dzmax = (int)sqrtf((float)best) + 1;   // safe overshoot
        int zlo = z - dzmax; if (zlo < 0) zlo = 0;
        int zhi = z + dzmax; if (zhi > 127) zhi = 127;
        #pragma unroll 4
        for (int zz = zlo; zz <= zhi; zz++) {
            int d = z - zz;
            int c = d * d + (int)col[zz * 16384];  // independent loads
            if (c < best) best = c;
        }
        if (best > lmax) lmax = best;
    }

    // block max over 128 threads -> one atomic per block
    #pragma unroll
    for (int off = 16; off; off >>= 1) {
        int o = __shfl_down_sync(0xFFFFFFFFu, lmax, off);
        if (o > lmax) lmax = o;
    }
    __shared__ int wmax[4];
    __shared__ int is_last;
    if ((tid & 31) == 0) wmax[tid >> 5] = lmax;
    __syncthreads();
    if (tid == 0) {
        int m = wmax[0];
        if (wmax[1] > m) m = wmax[1];
        if (wmax[2] > m) m = wmax[2];
        if (wmax[3] > m) m = wmax[3];
        if (m >= 0) atomicMax(&g_dirmax[qv], m);
        __threadfence();
        unsigned int d = atomicAdd(&g_done, 1u);
        is_last = (d == (unsigned int)(gridDim.x - 1));
    }
    __syncthreads();
    if (is_last && tid < 2) {            // last block finalizes both outputs
        int vA = 2 * tid, vB = 2 * tid + 1;
        bool empty = (g_cnt[vA] == 0) || (g_cnt[vB] == 0);
        int mA = atomicAdd(&g_dirmax[vA], 0);   // L2 read (bypass stale L1)
        int mB = atomicAdd(&g_dirmax[vB], 0);
        int m  = mA > mB ? mA : mB;
        out[tid] = empty ? CUDART_INF_F : sqrtf((float)m);
    }
}

// ============================================================================
extern "C" void kernel_launch(void* const* d_in, const int* in_sizes, int n_in,
                              void* d_out, int out_size)
{
    const float* inputs  = (const float*)d_in[0];
    const float* targets = (const float*)d_in[1];
    float* out = (float*)d_out;

    k_binarize   <<<8192, 256>>>(inputs, targets);
    k_edgephase2 <<<512, 128>>>();
    k_zmin       <<<1024, 128>>>(out);
}

// round 16
// speedup vs baseline: 1.3531x; 1.0803x over previous
#include <cuda_runtime.h>
#include <math_constants.h>

// Hausdorff distance between edge sets of two binary 128^3 masks, batch=2.
// Pipeline: bit-pack masks (float4 + shfl-assembled words) -> [fused] bitwise
// 3x3x3 edge extraction + exact 1D x-distance g (u8, via smem slice) +
// edge-voxel worklist compaction + Meijster envelope along y (smem stack) ->
// dt2 = exact 2D squared EDT per z-slice (u16) -> one thread per partner
// edge voxel: exact min over z within a precomputed radius bound ->
// directed max -> sqrt. Output: 2 floats.

#define DWH 128
#define NVOL 4                      // (b0,in) (b0,tgt) (b1,in) (b1,tgt)
#define VOXELS (128 * 128 * 128)
#define GCLAMP 222                  // 222^2 = 49284 > 3*127^2 -> lossless clamp
#define GPITCH 132                  // smem g row pitch (33 words, stride 1 bank)
#define STK_SM 48                   // smem stack depth; >=48 falls back to local

// ---- scratch: __device__ globals (no allocation allowed) ----
__device__ unsigned int   g_mask[NVOL][DWH][DWH][4];  // bit-packed masks, 1MB
__device__ unsigned short g_dt2[NVOL][VOXELS];        // 2D sq-EDT per slice, 16MB
__device__ unsigned int   g_list[NVOL][VOXELS];       // packed edge coords, 32MB
__device__ int            g_cnt[NVOL];                // edge counts / list sizes
__device__ int            g_dirmax[NVOL];             // directed max squared EDT
__device__ unsigned int   g_done;                     // k_zmin completion counter

// ============================================================================
// Kernel 1: binarize inputs (>0) into bit-packed masks.  [validated R12/R14]
// One warp per 128-float row; lane loads float4 -> nibble -> 3-step shfl_xor
// OR assembles each oct's 32-bit word; lanes 0/8/16/24 store words 0..3.
// Also zeroes the accumulators (consumed only by later kernels).
// ============================================================================
__global__ void __launch_bounds__(256) k_binarize(
    const float* __restrict__ inputs, const float* __restrict__ targets)
{
    int gt = blockIdx.x * blockDim.x + threadIdx.x;   // 2,097,152 threads
    if (gt < 9) {
        if (gt < 4)      g_cnt[gt] = 0;
        else if (gt < 8) g_dirmax[gt - 4] = 0;
        else             g_done = 0;
    }
    int lane = gt & 31;
    int wrp  = gt >> 5;              // 65536 warps, one per (v,z,y) row
    int v    = wrp >> 14;
    int rem  = wrp & 16383;
    int z    = rem >> 7;
    int y    = rem & 127;

    const float* src = (v & 1) ? targets : inputs;
    int b = v >> 1;
    const float4* row = (const float4*)(src + (size_t)b * VOXELS + z * 16384 + y * 128);
    float4 val = row[lane];

    unsigned int nib = (val.x > 0.0f ? 1u : 0u)
                     | (val.y > 0.0f ? 2u : 0u)
                     | (val.z > 0.0f ? 4u : 0u)
                     | (val.w > 0.0f ? 8u : 0u);
    unsigned int u = nib << ((lane & 7) * 4);
    u |= __shfl_xor_sync(0xFFFFFFFFu, u, 1);
    u |= __shfl_xor_sync(0xFFFFFFFFu, u, 2);
    u |= __shfl_xor_sync(0xFFFFFFFFu, u, 4);          // full word per 8-lane oct
    if ((lane & 7) == 0) g_mask[v][z][y][lane >> 3] = u;
}

// Exact C-truncation division num/den (den>0) via fast float divide + fixup.
// |num| < 2^17, den <= 254 -> float quotient error << 1 -> one-step fix.
__device__ __forceinline__ int trunc_div(int num, int den)
{
    int q = __float2int_rz(__fdividef((float)num, (float)den));
    int r = num - q * den;
    if (num >= 0) { q += (r >= den); q -= (r < 0); }
    else          { q += (r > 0);    q -= (r <= -den); }
    return q;
}

// ============================================================================
// Kernel 2 (FUSED edge + phase2), one block per (v,z) slice, 128 threads.
// Stage A (thread = y-row): edge = (~mask) & (3x3x3 box-OR of mask) bitwise;
//   worklist append; exact 1D x-distance g (u8, register byte-array) staged
//   into a smem slice [y][x] (pitch 132: conflict-free both ways).
//   [byte-identical to R12/R14 passing kernels]
// Stage B (thread = x-column): Meijster lower envelope along y over smem g:
//   dt2(x,y,z) = min_yy (y-yy)^2 + g(x,yy,z)^2  (exact 2D squared EDT).
//   Stack entries packed into one u32 (sq:7|tq:7|fsq:16); stack lives in
//   SHARED memory (lane-major [depth][128]: bank = lane mod 32 regardless of
//   per-lane depth -> conflict-free even under divergence) for depth < 48,
//   with a local-memory fallback for the (rare) deeper case. Values
//   identical to the validated version. Max dt2 = 65413 -> u16, no clamp.
// ============================================================================
__global__ void __launch_bounds__(128) k_edgephase2()
{
    __shared__ unsigned char gsm[128 * GPITCH];       // 16.9 KB g slice [y][x]
    __shared__ unsigned int  stSm[STK_SM * 128];      // 24.6 KB envelope stacks

    int b = blockIdx.x;                  // 512 = 4 volumes * 128 z-slices
    int v = b >> 7;
    int z = b & 127;
    int y = threadIdx.x;                 // stage A: thread = y-row

    // ---- stage A: edge bits for row (v,z,y) ----
    unsigned int a0 = 0, a1 = 0, a2 = 0, a3 = 0;
    #pragma unroll
    for (int dz = -1; dz <= 1; dz++) {
        int zz = z + dz;
        if (zz < 0 || zz > 127) continue;
        #pragma unroll
        for (int dy = -1; dy <= 1; dy++) {
            int yy = y + dy;
            if (yy < 0 || yy > 127) continue;
            const unsigned int* r = g_mask[v][zz][yy];
            a0 |= r[0]; a1 |= r[1]; a2 |= r[2]; a3 |= r[3];
        }
    }
    // dilate along x across the 128-bit row (word carries)
    unsigned int d0 = a0 | (a0 << 1)               | (a0 >> 1) | (a1 << 31);
    unsigned int d1 = a1 | (a1 << 1) | (a0 >> 31)  | (a1 >> 1) | (a2 << 31);
    unsigned int d2 = a2 | (a2 << 1) | (a1 >> 31)  | (a2 >> 1) | (a3 << 31);
    unsigned int d3 = a3 | (a3 << 1) | (a2 >> 31)  | (a3 >> 1);

    const unsigned int* m = g_mask[v][z][y];
    unsigned int ew[4];
    ew[0] = d0 & ~m[0]; ew[1] = d1 & ~m[1]; ew[2] = d2 & ~m[2]; ew[3] = d3 & ~m[3];

    // ---- worklist append (one reservation per row with any edges) ----
    int cnt = __popc(ew[0]) + __popc(ew[1]) + __popc(ew[2]) + __popc(ew[3]);
    if (cnt) {
        int idx = atomicAdd(&g_cnt[v], cnt);
        unsigned int* lst = g_list[v];
        unsigned int zy = ((unsigned int)z << 14) | ((unsigned int)y << 7);
        #pragma unroll
        for (int w = 0; w < 4; w++) {
            unsigned int bits = ew[w];
            while (bits) {
                int bit = __ffs(bits) - 1;
                bits &= bits - 1;
                lst[idx++] = zy | (unsigned int)(w * 32 + bit);
            }
        }
    }

    // ---- 1D x-distance g (exact, clamped at GCLAMP), registers -> smem ----
    unsigned int gr[32];                 // 128 u8 packed, static-indexed -> regs
    {
        int g = GCLAMP;
        #pragma unroll
        for (int w4 = 0; w4 < 32; w4++) {              // packs x = 4*w4 .. +3
            unsigned int word = ew[w4 >> 3];
            unsigned int packed = 0;
            #pragma unroll
            for (int j = 0; j < 4; j++) {
                int bit = (word >> (((w4 & 7) << 2) + j)) & 1;
                g = bit ? 0 : (g < GCLAMP ? g + 1 : GCLAMP);
                packed |= (unsigned int)g << (8 * j);
            }
            gr[w4] = packed;
        }
        int p = (gr[31] >> 24) & 0xFF;
        #pragma unroll
        for (int x = 126; x >= 0; x--) {
            int w4 = x >> 2, sh = (x & 3) << 3;
            int c = (gr[w4] >> sh) & 0xFF;
            int nv = p + 1;
            if (c < nv) nv = c;                        // nv <= GCLAMP always
            gr[w4] = (gr[w4] & ~(0xFFu << sh)) | ((unsigned int)nv << sh);
            p = nv;
        }
    }
    {
        unsigned int* row = (unsigned int*)&gsm[y * GPITCH];  // 132 % 4 == 0
        #pragma unroll
        for (int i = 0; i < 32; i++) row[i] = gr[i];   // stride-33-word: no bank conflicts
    }
    __syncthreads();

    // ---- stage B: Meijster envelope along y, thread = x column ----
    {
        int x = threadIdx.x;
        const unsigned char* gcol = &gsm[x];
        unsigned int* stCol = &stSm[x];  // thread-private smem column (lane-major)
        unsigned int  stLoc[128 - STK_SM];  // rare deep-stack fallback

        int q  = 0;                      // top level; stack[0..q-1] stored
        int sq = 0, tq = 0;
        int g0 = gcol[0];
        int fsq = g0 * g0;

        int gu = gcol[GPITCH];           // prefetched g[1]
        for (int u = 1; u < 128; u++) {
            int fu = gu * gu;
            int unext = (u < 127) ? u + 1 : 127;
            gu = gcol[unext * GPITCH];   // prefetch next (overlaps envelope ALU)

            for (;;) {
                int aa = tq - sq, bb = tq - u;
                if (aa * aa + fsq > bb * bb + fu) {    // incumbent loses at tq
                    if (q == 0) { q = -1; break; }
                    q--;
                    unsigned int pk = (q < STK_SM) ? stCol[q * 128]
                                                   : stLoc[q - STK_SM];
                    sq = pk & 127; tq = (pk >> 7) & 127; fsq = pk >> 14;
                } else break;
            }
            if (q < 0) { q = 0; sq = u; tq = 0; fsq = fu; }
            else {
                int du  = u - sq;                       // 1..127
                int num = (u + sq) * du + fu - fsq;     // u^2 - sq^2 + fu - fsq
                int w   = 1 + trunc_div(num, 2 * du);
                if (w < 128) {
                    unsigned int pk = (unsigned int)sq | ((unsigned int)tq << 7)
                                    | ((unsigned int)fsq << 14);
                    if (q < STK_SM) stCol[q * 128] = pk;
                    else            stLoc[q - STK_SM] = pk;
                    q++; sq = u; tq = w; fsq = fu;
                }
            }
        }

        unsigned short* dt = &g_dt2[v][z * 16384 + x];
        #pragma unroll 4
        for (int u = 127; u >= 0; u--) {
            int d = u - sq;
            dt[u * 128] = (unsigned short)(d * d + fsq);
            if (u == tq) {
                q--;
                if (q >= 0) {
                    unsigned int pk = (q < STK_SM) ? stCol[q * 128]
                                                   : stLoc[q - STK_SM];
                    sq = pk & 127; tq = (pk >> 7) & 127; fsq = pk >> 14;
                }
            }
        }
    }
}

// ============================================================================
// Kernel 3: one thread per partner edge voxel (grid-stride over the compacted
// worklist). For voxel q=(x,y,z) of volume qv:
//   EDT(q) = min_zz (z-zz)^2 + dt2_pv(x,y,zz)
// best0 = dt2_pv at zz=z (exact in-slice EDT) -> radius bound
// dzmax = floor(sqrt(best0))+1 (overshoot harmless). All threads independent.
// Directed max -> atomicMax; last finished block writes both outputs
// (atomic reads bypass a stale L1 line shared with g_cnt). [validated R10-R14]
// ============================================================================
__global__ void __launch_bounds__(128) k_zmin(float* __restrict__ out)
{
    int b   = blockIdx.x;                // 1024
    int qv  = b & 3;
    int pv  = qv ^ 1;
    int tid = threadIdx.x;

    int cnt = g_cnt[qv];                 // list size for this volume
    int lmax = -1;
    const unsigned int*   lst  = g_list[qv];
    const unsigned short* dtpv = g_dt2[pv];

    for (int i = (b >> 2) * 128 + tid; i < cnt; i += 256 * 128) {
        unsigned int e = lst[i];
        int x = e & 127;
        int y = (int)(e >> 7) & 127;
        int z = (int)(e >> 14);

        const unsigned short* col = dtpv + y * 128 + x;
        int best = (int)col[z * 16384];            // tight exact bound (dz=0)
        int dzmax = (int)sqrtf((float)best) + 1;   // safe overshoot
        int zlo = z - dzmax; if (zlo < 0) zlo = 0;
        int zhi = z + dzmax; if (zhi > 127) zhi = 127;
        #pragma unroll 4
        for (int zz = zlo; zz <= zhi; zz++) {
            int d = z - zz;
            int c = d * d + (int)col[zz * 16384];  // independent loads
            if (c < best) best = c;
        }
        if (best > lmax) lmax = best;
    }

    // block max over 128 threads -> one atomic per block
    #pragma unroll
    for (int off = 16; off; off >>= 1) {
        int o = __shfl_down_sync(0xFFFFFFFFu, lmax, off);
        if (o > lmax) lmax = o;
    }
    __shared__ int wmax[4];
    __shared__ int is_last;
    if ((tid & 31) == 0) wmax[tid >> 5] = lmax;
    __syncthreads();
    if (tid == 0) {
        int m = wmax[0];
        if (wmax[1] > m) m = wmax[1];
        if (wmax[2] > m) m = wmax[2];
        if (wmax[3] > m) m = wmax[3];
        if (m >= 0) atomicMax(&g_dirmax[qv], m);
        __threadfence();
        unsigned int d = atomicAdd(&g_done, 1u);
        is_last = (d == (unsigned int)(gridDim.x - 1));
    }
    __syncthreads();
    if (is_last && tid < 2) {            // last block finalizes both outputs
        int vA = 2 * tid, vB = 2 * tid + 1;
        bool empty = (g_cnt[vA] == 0) || (g_cnt[vB] == 0);
        int mA = atomicAdd(&g_dirmax[vA], 0);   // L2 read (bypass stale L1)
        int mB = atomicAdd(&g_dirmax[vB], 0);
        int m  = mA > mB ? mA : mB;
        out[tid] = empty ? CUDART_INF_F : sqrtf((float)m);
    }
}

// ============================================================================
extern "C" void kernel_launch(void* const* d_in, const int* in_sizes, int n_in,
                              void* d_out, int out_size)
{
    const float* inputs  = (const float*)d_in[0];
    const float* targets = (const float*)d_in[1];
    float* out = (float*)d_out;

    k_binarize   <<<8192, 256>>>(inputs, targets);
    k_edgephase2 <<<512, 128>>>();
    k_zmin       <<<1024, 128>>>(out);
}